// round 7
// baseline (speedup 1.0000x reference)
#include <cuda_runtime.h>
#include <math.h>
#include <float.h>

#define BB 64
#define CC 100
#define KK 5
#define NN (BB*CC*KK)      // 32000
#define NBINS 8192
#define NLB 64             // Team L blocks (L1 chain)
#define GRPL (NBINS/NLB)   // 128 bins per L block
#define NBLK 128
#define NTHR 256
#define NPB (NN/NLB)       // 500 elements per L block
#define NAB 40             // blocks active in Phase A (320 warp tasks / 8)
#define DMINF (-8.0f)
#define INVWF 512.0f       // NBINS / 16

// ---------------- device scratch (no allocs allowed) ----------------
__device__ float4 g_pack[NN];          // (t, s, d, 0)
__device__ float4 g_sorted[NN];        // (d, t, s, 0) bin-sorted
__device__ float4 g_hist[NBINS];       // (count, sumT, sumS, 0) via float atomics
__device__ float4 g_binPack[NBINS];    // (inclT_loc, inclS_loc, offExcC_loc, count)
__device__ float4 g_aggL[NLB];         // (aggT, aggS, aggC, flag)
__device__ float4 g_aflag[NAB];        // Phase-A completion flags
__device__ int    g_cur[NBINS];
__device__ float  g_tk[KK*BB*CC], g_sk[KK*BB*CC];   // [k][b][c]
__device__ double g_tt, g_ss, g_ts, g_kl[KK], g_ce, g_l1, g_sub;
__device__ unsigned g_done;
__device__ volatile unsigned g_barLGen;
__device__ unsigned g_barLCnt;

__device__ __forceinline__ int binOf(float x){
    int j = (int)floorf((x - DMINF) * INVWF);
    return min(max(j, 0), NBINS-1);   // clamp is exact: boundary bin is scanned element-wise
}
__device__ __forceinline__ float4 ldvol4(const float4* p){
    float4 v;
    asm volatile("ld.volatile.global.v4.f32 {%0,%1,%2,%3}, [%4];"
                 : "=f"(v.x),"=f"(v.y),"=f"(v.z),"=f"(v.w) : "l"(p));
    return v;
}
__device__ __forceinline__ void stvol4(float4* p, float4 v){
    asm volatile("st.volatile.global.v4.f32 [%0], {%1,%2,%3,%4};"
                 :: "l"(p), "f"(v.x),"f"(v.y),"f"(v.z),"f"(v.w) : "memory");
}

// Team L barrier (64 blocks), generation-based, replay-safe
__device__ __forceinline__ void teamBarL(){
    __threadfence();
    __syncthreads();
    if (threadIdx.x == 0){
        unsigned gen = g_barLGen;
        if (atomicAdd(&g_barLCnt, 1u) == NLB-1u){
            g_barLCnt = 0u;
            __threadfence();
            g_barLGen = gen + 1u;
        } else {
            while (g_barLGen == gen) { __nanosleep(32); }
            __threadfence();
        }
    }
    __syncthreads();
}

__device__ __forceinline__ float blockSum(float v, float* shR){
    int lane = threadIdx.x & 31, w = threadIdx.x >> 5;
    #pragma unroll
    for (int o=16;o;o>>=1) v += __shfl_down_sync(0xffffffffu, v, o);
    if (lane==0) shR[w] = v;
    __syncthreads();
    float r = 0.f;
    if (threadIdx.x==0){
        #pragma unroll
        for (int i=0;i<NTHR/32;i++) r += shR[i];
    }
    __syncthreads();
    return r;   // valid on tid 0 only
}

__global__ void __launch_bounds__(NTHR)
fused_kernel(const float* __restrict__ ls, const float* __restrict__ lt,
             const int* __restrict__ tgt, float* __restrict__ out)
{
    __shared__ float shC[NTHR], shA[NTHR], shB[NTHR];
    __shared__ float shOffC[NLB], shOffT[NLB], shOffS[NLB];
    __shared__ float shTotT, shTotS;
    __shared__ float shR[NTHR/32];

    const int tid  = threadIdx.x;
    const int bid  = blockIdx.x;
    const int lane = tid & 31;
    const int wid  = tid >> 5;

    // ============ Phase A: softmax + KD + L2 dots + histogram (blocks 0..39) ============
    if (bid < NAB){
        int gw = bid*(NTHR/32) + wid;          // always < 320
        int b = gw / KK, k = gw % KK;
        float invT = 1.0f / (float)(k+1);
        float av[4], bv[4];
        float amax = -FLT_MAX, bmax = -FLT_MAX;
        #pragma unroll
        for (int q=0;q<4;q++){
            int c = lane + 32*q;
            bool ok = c < CC;
            av[q] = ok ? ls[b*CC+c]*invT : -FLT_MAX;
            bv[q] = ok ? lt[b*CC+c]*invT : -FLT_MAX;
            amax = fmaxf(amax, av[q]);
            bmax = fmaxf(bmax, bv[q]);
        }
        #pragma unroll
        for (int o=16;o;o>>=1){
            amax = fmaxf(amax, __shfl_xor_sync(0xffffffffu, amax, o));
            bmax = fmaxf(bmax, __shfl_xor_sync(0xffffffffu, bmax, o));
        }
        float ea[4], eb[4], sumA = 0.f, sumB = 0.f;
        #pragma unroll
        for (int q=0;q<4;q++){
            int c = lane + 32*q;
            ea[q] = (c<CC) ? expf(av[q]-amax) : 0.f;
            eb[q] = (c<CC) ? expf(bv[q]-bmax) : 0.f;
            sumA += ea[q]; sumB += eb[q];
        }
        #pragma unroll
        for (int o=16;o;o>>=1){
            sumA += __shfl_xor_sync(0xffffffffu, sumA, o);
            sumB += __shfl_xor_sync(0xffffffffu, sumB, o);
        }
        float lA = logf(sumA), lB = logf(sumB);
        float rA = 1.f/sumA, rB = 1.f/sumB;
        int tg = (k==0) ? tgt[b] : -1;
        float kl=0.f, tt=0.f, ssv=0.f, tsv=0.f;
        #pragma unroll
        for (int q=0;q<4;q++){
            int c = lane + 32*q;
            if (c < CC){
                float lq = av[q]-amax-lA;
                float lp = bv[q]-bmax-lB;
                float sv = ea[q]*rA;
                float tv = eb[q]*rB;
                float dv = lp - lq;
                int idx = (b*CC + c)*KK + k;
                g_pack[idx] = make_float4(tv, sv, dv, 0.f);
                int i2 = (k*BB + b)*CC + c;
                g_tk[i2]=tv; g_sk[i2]=sv;
                int j = binOf(dv);
                atomicAdd(&g_hist[j].x, 1.0f);
                atomicAdd(&g_hist[j].y, tv);
                atomicAdd(&g_hist[j].z, sv);
                kl  += tv*dv;
                tt  += tv*tv;
                ssv += sv*sv;
                tsv += tv*sv;
                if (c == tg) atomicAdd(&g_ce, (double)(-lq));
            }
        }
        #pragma unroll
        for (int o=16;o;o>>=1){
            kl  += __shfl_xor_sync(0xffffffffu, kl,  o);
            tt  += __shfl_xor_sync(0xffffffffu, tt,  o);
            ssv += __shfl_xor_sync(0xffffffffu, ssv, o);
            tsv += __shfl_xor_sync(0xffffffffu, tsv, o);
        }
        if (lane==0){
            atomicAdd(&g_kl[k], (double)kl);
            atomicAdd(&g_tt, (double)tt);
            atomicAdd(&g_ss, (double)ssv);
            atomicAdd(&g_ts, (double)tsv);
        }
        __threadfence();
        __syncthreads();
        if (tid==0) stvol4(&g_aflag[bid], make_float4(0.f,0.f,0.f,1.f));
    }

    // ---- all blocks wait for Phase A completion (40 flags) ----
    if (tid < NAB){
        for(;;){ float4 a = ldvol4(&g_aflag[tid]); if (a.w != 0.f) break; __nanosleep(32); }
    }
    __threadfence();
    __syncthreads();

    if (bid < NLB){
        // =================== TEAM L: bin scan -> scatter -> L1 ===================
        // --- local exclusive scan of this block's 128-bin group (1 bin/thread, tid<128) ---
        int base = bid*GRPL;
        float c0=0.f, t0=0.f, s0=0.f;
        if (tid < GRPL){
            float4 h = g_hist[base + tid];
            c0=h.x; t0=h.y; s0=h.z;
        }
        shC[tid]=c0; shA[tid]=t0; shB[tid]=s0;
        __syncthreads();
        for (int off=1; off<GRPL; off<<=1){
            float vC=shC[tid], vT=shA[tid], vS=shB[tid];
            float uC=0.f,uT=0.f,uS=0.f;
            if (tid>=off && tid<GRPL){ uC=shC[tid-off]; uT=shA[tid-off]; uS=shB[tid-off]; }
            __syncthreads();
            if (tid<GRPL){ shC[tid]=vC+uC; shA[tid]=vT+uT; shB[tid]=vS+uS; }
            __syncthreads();
        }
        if (tid < GRPL){
            float exC = tid? shC[tid-1]:0.f;
            // inclusive T/S prefixes, exclusive count offset
            g_binPack[base+tid] = make_float4(shA[tid], shB[tid], exC, c0);
        }
        float aggC=shC[GRPL-1], aggT=shA[GRPL-1], aggS=shB[GRPL-1];
        __threadfence();
        __syncthreads();
        if (tid==0) stvol4(&g_aggL[bid], make_float4(aggT, aggS, aggC, 1.0f));

        // --- gather all 64 group aggregates (flag-in-payload) ---
        if (tid < NLB){
            float4 a;
            for(;;){ a = ldvol4(&g_aggL[tid]); if (a.w != 0.f) break; __nanosleep(32); }
            shC[tid]=a.z; shA[tid]=a.x; shB[tid]=a.y;
        }
        __threadfence();
        __syncthreads();
        for (int off=1; off<NLB; off<<=1){
            float vC=0.f,vT=0.f,vS=0.f,uC=0.f,uT=0.f,uS=0.f;
            if (tid < NLB){
                vC=shC[tid]; vT=shA[tid]; vS=shB[tid];
                if (tid>=off){ uC=shC[tid-off]; uT=shA[tid-off]; uS=shB[tid-off]; }
            }
            __syncthreads();
            if (tid < NLB){ shC[tid]=vC+uC; shA[tid]=vT+uT; shB[tid]=vS+uS; }
            __syncthreads();
        }
        if (tid < NLB){
            shOffC[tid] = tid? shC[tid-1] : 0.f;
            shOffT[tid] = tid? shA[tid-1] : 0.f;
            shOffS[tid] = tid? shB[tid-1] : 0.f;
        }
        if (tid==0){ shTotT = shA[NLB-1]; shTotS = shB[NLB-1]; }
        __syncthreads();

        // --- scatter this block's 500 elements into bin-sorted order ---
        for (int i=tid; i<NPB; i+=NTHR){
            int id = bid*NPB + i;
            float4 p = g_pack[id];
            int j = binOf(p.z);
            int g = j >> 7;                   // /GRPL
            float4 bp = g_binPack[j];
            int pos = (int)shOffC[g] + (int)bp.z + atomicAdd(&g_cur[j], 1);
            g_sorted[pos] = make_float4(p.z, p.x, p.y, 0.f);
        }
        teamBarL();

        // --- L1 reduction: P_t(a) = suffix of bins + exact boundary-bin scan ---
        float contrib = 0.f;
        float Ttot = shTotT, Stot = shTotS;
        for (int i=tid; i<NPB; i+=NTHR){
            int id = bid*NPB + i;
            float4 p = g_pack[id];              // t=x, s=y, d=z
            float x = -p.z;
            int j = binOf(x);
            int g = j >> 7;
            float4 bp = g_binPack[j];
            float pt = Ttot - (shOffT[g] + bp.x);
            float ps = Stot - (shOffS[g] + bp.y);
            int e0 = (int)shOffC[g] + (int)bp.z;
            int cnt = (int)bp.w;
            for (int m=e0; m<e0+cnt; ++m){
                float4 e = g_sorted[m];
                if (e.x > x){ pt += e.y; ps += e.z; }
            }
            contrib += p.x*(2.f*pt - Ttot) - p.y*(2.f*ps - Stot);
        }
        float r2 = blockSum(contrib, shR);
        if (tid==0) atomicAdd(&g_l1, (double)r2);

        // --- cleanup for next replay (readers done after teamBarL) ---
        float4 z4 = make_float4(0.f,0.f,0.f,0.f);
        if (tid < GRPL){
            g_hist[base+tid] = z4;
            g_cur[base+tid] = 0;
        }
        if (tid==0) g_aggL[bid] = z4;
    } else {
        // =================== TEAM G: Gram sub losses, 4x4 tiles ===================
        const int NTG = KK*16*16;   // 1280 (BxB in 4x4 tiles)
        const int NTH = KK*25*25;   // 3125 (CxC in 4x4 tiles)
        int gid = (bid-NLB)*NTHR + tid;
        float val = 0.f;
        if (gid < NTG){
            int k  = gid >> 8;
            int r  = gid & 255;
            int i0 = (r >> 4) << 2;
            int j0 = (r & 15) << 2;
            const float* T = g_tk + k*BB*CC;
            const float* S = g_sk + k*BB*CC;
            float acc[16];
            #pragma unroll
            for (int q=0;q<16;q++) acc[q]=0.f;
            for (int c=0;c<CC;c++){
                float ti[4], tj[4], si[4], sj[4];
                #pragma unroll
                for (int d2=0;d2<4;d2++){
                    ti[d2]=T[(i0+d2)*CC+c]; tj[d2]=T[(j0+d2)*CC+c];
                    si[d2]=S[(i0+d2)*CC+c]; sj[d2]=S[(j0+d2)*CC+c];
                }
                #pragma unroll
                for (int di=0;di<4;di++)
                    #pragma unroll
                    for (int dj=0;dj<4;dj++)
                        acc[di*4+dj] += ti[di]*tj[dj] - si[di]*sj[dj];
            }
            #pragma unroll
            for (int q=0;q<16;q++) val += acc[q]*acc[q];
        } else if (gid < NTG + NTH){
            int u  = gid - NTG;
            int k  = u / 625;
            int r  = u - k*625;
            int i0 = (r / 25) * 4;
            int j0 = (r % 25) * 4;
            const float* T = g_tk + k*BB*CC;
            const float* S = g_sk + k*BB*CC;
            float acc[16];
            #pragma unroll
            for (int q=0;q<16;q++) acc[q]=0.f;
            for (int b2=0;b2<BB;b2++){
                float4 t4i = *(const float4*)(T + b2*CC + i0);
                float4 t4j = *(const float4*)(T + b2*CC + j0);
                float4 s4i = *(const float4*)(S + b2*CC + i0);
                float4 s4j = *(const float4*)(S + b2*CC + j0);
                float ti[4]={t4i.x,t4i.y,t4i.z,t4i.w};
                float tj[4]={t4j.x,t4j.y,t4j.z,t4j.w};
                float si[4]={s4i.x,s4i.y,s4i.z,s4i.w};
                float sj[4]={s4j.x,s4j.y,s4j.z,s4j.w};
                #pragma unroll
                for (int di=0;di<4;di++)
                    #pragma unroll
                    for (int dj=0;dj<4;dj++)
                        acc[di*4+dj] += ti[di]*tj[dj] - si[di]*sj[dj];
            }
            #pragma unroll
            for (int q=0;q<16;q++) val += acc[q]*acc[q];
        }
        float r2 = blockSum(val, shR);
        if (tid==0) atomicAdd(&g_sub, (double)r2);
    }

    // ============ Last block out does the final combine (no grid barrier) ============
    __threadfence();
    __syncthreads();
    if (tid == 0){
        if (atomicAdd(&g_done, 1u) == NBLK-1u){
            __threadfence();
            double ce = g_ce / (double)BB;
            double kd = 0.0;
            #pragma unroll
            for (int k=0;k<KK;k++){
                double T = (double)(k+1);
                kd += (g_kl[k] / (double)(BB*CC)) * (0.7*T*T) + ce * 0.3;
            }
            double tt=g_tt, ss2=g_ss, ts2=g_ts;
            double l2 = 0.00025*(tt*tt - 2.0*ts2*ts2 + ss2*ss2);
            out[0] = (float)(kd + 0.00025*g_l1 + l2 + g_sub);
            // reset state for next graph replay
            g_tt = 0.0; g_ss = 0.0; g_ts = 0.0;
            g_ce = 0.0; g_l1 = 0.0; g_sub = 0.0;
            #pragma unroll
            for (int k=0;k<KK;k++) g_kl[k] = 0.0;
            float4 z4 = make_float4(0.f,0.f,0.f,0.f);
            for (int i=0;i<NAB;i++) g_aflag[i] = z4;
            g_done = 0u;
        }
    }
}

// ---------------- launch ----------------
extern "C" void kernel_launch(void* const* d_in, const int* in_sizes, int n_in,
                              void* d_out, int out_size){
    (void)in_sizes; (void)n_in; (void)out_size;
    const float* ls  = (const float*)d_in[0];  // logits_student [64,100]
    const float* lt  = (const float*)d_in[1];  // logits_teacher [64,100]
    const int*   tgt = (const int*)  d_in[2];  // target [64]
    float* out = (float*)d_out;

    fused_kernel<<<NBLK, NTHR>>>(ls, lt, tgt, out);
}

// round 8
// speedup vs baseline: 1.0336x; 1.0336x over previous
#include <cuda_runtime.h>
#include <math.h>
#include <float.h>

#define BB 64
#define CC 100
#define KK 5
#define NN (BB*CC*KK)      // 32000
#define NBINS 16384
#define NLB 64             // Team L blocks
#define GRPL (NBINS/NLB)   // 256 bins per L block = 1 per thread
#define NBLK 128
#define NTHR 256
#define NPB (NN/NLB)       // 500 elements per L block
#define NAB 40             // blocks active in Phase A (320 warp tasks / 8)
#define DMINF (-20.0f)
#define INVWF 409.6f       // NBINS / 40

// ---------------- device scratch (no allocs allowed) ----------------
__device__ float4 g_pack[NN];          // (t, s, d, 0)
__device__ float4 g_hist[NBINS];       // (sumT, sumS, -, -) via float atomics
__device__ float4 g_binPack[NBINS];    // (inclT_loc, inclS_loc, binT, binS)
__device__ float4 g_aggL[NLB];         // (aggT, aggS, -, flag)
__device__ float4 g_aflag[NAB];        // Phase-A completion flags
__device__ float  g_tk[KK*BB*CC], g_sk[KK*BB*CC];   // [k][b][c]
__device__ double g_tt, g_ss, g_ts, g_kl[KK], g_ce, g_l1, g_sub;
__device__ unsigned g_done;

__device__ __forceinline__ int binOf(float x){
    int j = (int)floorf((x - DMINF) * INVWF);
    return min(max(j, 0), NBINS-1);
}
__device__ __forceinline__ float4 ldvol4(const float4* p){
    float4 v;
    asm volatile("ld.volatile.global.v4.f32 {%0,%1,%2,%3}, [%4];"
                 : "=f"(v.x),"=f"(v.y),"=f"(v.z),"=f"(v.w) : "l"(p));
    return v;
}
__device__ __forceinline__ void stvol4(float4* p, float4 v){
    asm volatile("st.volatile.global.v4.f32 [%0], {%1,%2,%3,%4};"
                 :: "l"(p), "f"(v.x),"f"(v.y),"f"(v.z),"f"(v.w) : "memory");
}

__device__ __forceinline__ float blockSum(float v, float* shR){
    int lane = threadIdx.x & 31, w = threadIdx.x >> 5;
    #pragma unroll
    for (int o=16;o;o>>=1) v += __shfl_down_sync(0xffffffffu, v, o);
    if (lane==0) shR[w] = v;
    __syncthreads();
    float r = 0.f;
    if (threadIdx.x==0){
        #pragma unroll
        for (int i=0;i<NTHR/32;i++) r += shR[i];
    }
    __syncthreads();
    return r;   // valid on tid 0 only
}

__global__ void __launch_bounds__(NTHR)
fused_kernel(const float* __restrict__ ls, const float* __restrict__ lt,
             const int* __restrict__ tgt, float* __restrict__ out)
{
    __shared__ float shA[NTHR], shB[NTHR];
    __shared__ float shOffT[NLB], shOffS[NLB];
    __shared__ float shTotT, shTotS;
    __shared__ float shR[NTHR/32];

    const int tid  = threadIdx.x;
    const int bid  = blockIdx.x;
    const int lane = tid & 31;
    const int wid  = tid >> 5;

    // ============ Phase A: softmax + KD + L2 dots + histogram (blocks 0..39) ============
    if (bid < NAB){
        int gw = bid*(NTHR/32) + wid;          // always < 320
        int b = gw / KK, k = gw % KK;
        float invT = 1.0f / (float)(k+1);
        float av[4], bv[4];
        float amax = -FLT_MAX, bmax = -FLT_MAX;
        #pragma unroll
        for (int q=0;q<4;q++){
            int c = lane + 32*q;
            bool ok = c < CC;
            av[q] = ok ? ls[b*CC+c]*invT : -FLT_MAX;
            bv[q] = ok ? lt[b*CC+c]*invT : -FLT_MAX;
            amax = fmaxf(amax, av[q]);
            bmax = fmaxf(bmax, bv[q]);
        }
        #pragma unroll
        for (int o=16;o;o>>=1){
            amax = fmaxf(amax, __shfl_xor_sync(0xffffffffu, amax, o));
            bmax = fmaxf(bmax, __shfl_xor_sync(0xffffffffu, bmax, o));
        }
        float ea[4], eb[4], sumA = 0.f, sumB = 0.f;
        #pragma unroll
        for (int q=0;q<4;q++){
            int c = lane + 32*q;
            ea[q] = (c<CC) ? expf(av[q]-amax) : 0.f;
            eb[q] = (c<CC) ? expf(bv[q]-bmax) : 0.f;
            sumA += ea[q]; sumB += eb[q];
        }
        #pragma unroll
        for (int o=16;o;o>>=1){
            sumA += __shfl_xor_sync(0xffffffffu, sumA, o);
            sumB += __shfl_xor_sync(0xffffffffu, sumB, o);
        }
        float lA = logf(sumA), lB = logf(sumB);
        float rA = 1.f/sumA, rB = 1.f/sumB;
        int tg = (k==0) ? tgt[b] : -1;
        float kl=0.f, tt=0.f, ssv=0.f, tsv=0.f;
        #pragma unroll
        for (int q=0;q<4;q++){
            int c = lane + 32*q;
            if (c < CC){
                float lq = av[q]-amax-lA;
                float lp = bv[q]-bmax-lB;
                float sv = ea[q]*rA;
                float tv = eb[q]*rB;
                float dv = lp - lq;
                int idx = (b*CC + c)*KK + k;
                g_pack[idx] = make_float4(tv, sv, dv, 0.f);
                int i2 = (k*BB + b)*CC + c;
                g_tk[i2]=tv; g_sk[i2]=sv;
                int j = binOf(dv);
                atomicAdd(&g_hist[j].x, tv);
                atomicAdd(&g_hist[j].y, sv);
                kl  += tv*dv;
                tt  += tv*tv;
                ssv += sv*sv;
                tsv += tv*sv;
                if (c == tg) atomicAdd(&g_ce, (double)(-lq));
            }
        }
        #pragma unroll
        for (int o=16;o;o>>=1){
            kl  += __shfl_xor_sync(0xffffffffu, kl,  o);
            tt  += __shfl_xor_sync(0xffffffffu, tt,  o);
            ssv += __shfl_xor_sync(0xffffffffu, ssv, o);
            tsv += __shfl_xor_sync(0xffffffffu, tsv, o);
        }
        if (lane==0){
            atomicAdd(&g_kl[k], (double)kl);
            atomicAdd(&g_tt, (double)tt);
            atomicAdd(&g_ss, (double)ssv);
            atomicAdd(&g_ts, (double)tsv);
        }
        __threadfence();
        __syncthreads();
        if (tid==0) stvol4(&g_aflag[bid], make_float4(0.f,0.f,0.f,1.f));
    }

    // ---- all blocks wait for Phase A completion (40 flags, pure spin) ----
    if (tid < NAB){
        for(;;){ float4 a = ldvol4(&g_aflag[tid]); if (a.w != 0.f) break; }
    }
    __threadfence();
    __syncthreads();

    if (bid < NLB){
        // =================== TEAM L: bin scan -> direct L1 lookup ===================
        // --- inclusive scan of this block's 256-bin group, 1 bin/thread ---
        int base = bid*GRPL;
        float4 h = g_hist[base + tid];
        float t0 = h.x, s0 = h.y;
        shA[tid]=t0; shB[tid]=s0;
        __syncthreads();
        #pragma unroll
        for (int off=1; off<NTHR; off<<=1){
            float vT=shA[tid], vS=shB[tid];
            float uT=0.f,uS=0.f;
            if (tid>=off){ uT=shA[tid-off]; uS=shB[tid-off]; }
            __syncthreads();
            shA[tid]=vT+uT; shB[tid]=vS+uS;
            __syncthreads();
        }
        g_binPack[base+tid] = make_float4(shA[tid], shB[tid], t0, s0);
        float aggT=shA[NTHR-1], aggS=shB[NTHR-1];
        __threadfence();
        __syncthreads();
        if (tid==0) stvol4(&g_aggL[bid], make_float4(aggT, aggS, 0.f, 1.0f));

        // --- gather all 64 group aggregates (flag-in-payload, pure spin) ---
        if (tid < NLB){
            float4 a;
            for(;;){ a = ldvol4(&g_aggL[tid]); if (a.w != 0.f) break; }
            shA[tid]=a.x; shB[tid]=a.y;
        }
        __threadfence();
        __syncthreads();
        #pragma unroll
        for (int off=1; off<NLB; off<<=1){
            float vT=0.f,vS=0.f,uT=0.f,uS=0.f;
            if (tid < NLB){
                vT=shA[tid]; vS=shB[tid];
                if (tid>=off){ uT=shA[tid-off]; uS=shB[tid-off]; }
            }
            __syncthreads();
            if (tid < NLB){ shA[tid]=vT+uT; shB[tid]=vS+uS; }
            __syncthreads();
        }
        if (tid < NLB){
            shOffT[tid] = tid? shA[tid-1] : 0.f;
            shOffS[tid] = tid? shB[tid-1] : 0.f;
        }
        if (tid==0){ shTotT = shA[NLB-1]; shTotS = shB[NLB-1]; }
        __syncthreads();

        // --- L1 reduction: P_t(a) = suffix above bin(-d_a) + half of that bin ---
        // boundary pairs have |d_a+d_b| < w so their |t t - s s| <= t t * w: half-split
        // error is second-order tiny (well under the 1e-3 rel tolerance).
        float contrib = 0.f;
        float Ttot = shTotT, Stot = shTotS;
        for (int i=tid; i<NPB; i+=NTHR){
            int id = bid*NPB + i;
            float4 p = g_pack[id];              // t=x, s=y, d=z
            float x = -p.z;
            int j = binOf(x);
            int g = j >> 8;                     // /GRPL
            float4 bp = g_binPack[j];           // inclT, inclS, binT, binS
            float pt = Ttot - (shOffT[g] + bp.x) + 0.5f*bp.z;
            float ps = Stot - (shOffS[g] + bp.y) + 0.5f*bp.w;
            contrib += p.x*(2.f*pt - Ttot) - p.y*(2.f*ps - Stot);
        }
        float r2 = blockSum(contrib, shR);
        if (tid==0) atomicAdd(&g_l1, (double)r2);

        // --- cleanup for next replay ---
        g_hist[base+tid] = make_float4(0.f,0.f,0.f,0.f);
        if (tid==0) g_aggL[bid] = make_float4(0.f,0.f,0.f,0.f);
    } else {
        // =================== TEAM G: Gram sub losses, 4x4 tiles ===================
        const int NTG = KK*16*16;   // 1280 (BxB in 4x4 tiles)
        const int NTH = KK*25*25;   // 3125 (CxC in 4x4 tiles)
        int gid = (bid-NLB)*NTHR + tid;
        float val = 0.f;
        if (gid < NTG){
            int k  = gid >> 8;
            int r  = gid & 255;
            int i0 = (r >> 4) << 2;
            int j0 = (r & 15) << 2;
            const float* T = g_tk + k*BB*CC;
            const float* S = g_sk + k*BB*CC;
            float acc[16];
            #pragma unroll
            for (int q=0;q<16;q++) acc[q]=0.f;
            for (int c=0;c<CC;c++){
                float ti[4], tj[4], si[4], sj[4];
                #pragma unroll
                for (int d2=0;d2<4;d2++){
                    ti[d2]=T[(i0+d2)*CC+c]; tj[d2]=T[(j0+d2)*CC+c];
                    si[d2]=S[(i0+d2)*CC+c]; sj[d2]=S[(j0+d2)*CC+c];
                }
                #pragma unroll
                for (int di=0;di<4;di++)
                    #pragma unroll
                    for (int dj=0;dj<4;dj++)
                        acc[di*4+dj] += ti[di]*tj[dj] - si[di]*sj[dj];
            }
            #pragma unroll
            for (int q=0;q<16;q++) val += acc[q]*acc[q];
        } else if (gid < NTG + NTH){
            int u  = gid - NTG;
            int k  = u / 625;
            int r  = u - k*625;
            int i0 = (r / 25) * 4;
            int j0 = (r % 25) * 4;
            const float* T = g_tk + k*BB*CC;
            const float* S = g_sk + k*BB*CC;
            float acc[16];
            #pragma unroll
            for (int q=0;q<16;q++) acc[q]=0.f;
            for (int b2=0;b2<BB;b2++){
                float4 t4i = *(const float4*)(T + b2*CC + i0);
                float4 t4j = *(const float4*)(T + b2*CC + j0);
                float4 s4i = *(const float4*)(S + b2*CC + i0);
                float4 s4j = *(const float4*)(S + b2*CC + j0);
                float ti[4]={t4i.x,t4i.y,t4i.z,t4i.w};
                float tj[4]={t4j.x,t4j.y,t4j.z,t4j.w};
                float si[4]={s4i.x,s4i.y,s4i.z,s4i.w};
                float sj[4]={s4j.x,s4j.y,s4j.z,s4j.w};
                #pragma unroll
                for (int di=0;di<4;di++)
                    #pragma unroll
                    for (int dj=0;dj<4;dj++)
                        acc[di*4+dj] += ti[di]*tj[dj] - si[di]*sj[dj];
            }
            #pragma unroll
            for (int q=0;q<16;q++) val += acc[q]*acc[q];
        }
        float r2 = blockSum(val, shR);
        if (tid==0) atomicAdd(&g_sub, (double)r2);
    }

    // ============ Last block out does the final combine (no grid barrier) ============
    __threadfence();
    __syncthreads();
    if (tid == 0){
        if (atomicAdd(&g_done, 1u) == NBLK-1u){
            __threadfence();
            double ce = g_ce / (double)BB;
            double kd = 0.0;
            #pragma unroll
            for (int k=0;k<KK;k++){
                double T = (double)(k+1);
                kd += (g_kl[k] / (double)(BB*CC)) * (0.7*T*T) + ce * 0.3;
            }
            double tt=g_tt, ss2=g_ss, ts2=g_ts;
            double l2 = 0.00025*(tt*tt - 2.0*ts2*ts2 + ss2*ss2);
            out[0] = (float)(kd + 0.00025*g_l1 + l2 + g_sub);
            // reset state for next graph replay
            g_tt = 0.0; g_ss = 0.0; g_ts = 0.0;
            g_ce = 0.0; g_l1 = 0.0; g_sub = 0.0;
            #pragma unroll
            for (int k=0;k<KK;k++) g_kl[k] = 0.0;
            float4 z4 = make_float4(0.f,0.f,0.f,0.f);
            for (int i=0;i<NAB;i++) g_aflag[i] = z4;
            g_done = 0u;
        }
    }
}

// ---------------- launch ----------------
extern "C" void kernel_launch(void* const* d_in, const int* in_sizes, int n_in,
                              void* d_out, int out_size){
    (void)in_sizes; (void)n_in; (void)out_size;
    const float* ls  = (const float*)d_in[0];  // logits_student [64,100]
    const float* lt  = (const float*)d_in[1];  // logits_teacher [64,100]
    const int*   tgt = (const int*)  d_in[2];  // target [64]
    float* out = (float*)d_out;

    fused_kernel<<<NBLK, NTHR>>>(ls, lt, tgt, out);
}